// round 16
// baseline (speedup 1.0000x reference)
#include <cuda_runtime.h>
#include <cuda_fp16.h>
#include <cstdint>

// SpGraphTransAttention on GB300.
// Outputs (flattened tuple): attention [E,4] | v [N,16,4] | prods [E,4]
// Softmax identity: exp(p-max)/sum == exp(p)/sum (p tiny) -> no max pass.
// QKV on tensor cores via ldmatrix + mma.sync.m16n8k16 (f16 in, f32 acc).
// q,k stored fp16 (128B rows); edge gathers one 128B line per row per edge.

#define NN_MAX 50000
#define NATT 64

__device__ __half g_qh[NN_MAX * NATT];
__device__ __half g_kh[NN_MAX * NATT];
__device__ float  g_denom[NN_MAX * 4];

__device__ __forceinline__ uint32_t smem_u32(const void* p) {
    return (uint32_t)__cvta_generic_to_shared(p);
}

// QKV via mma.sync. Grid (ceil(n/64), 3); blockIdx.y = matrix. 128 threads.
// Warp w computes nodes [base + 16w, +16) x all 64 columns.
__global__ void __launch_bounds__(128) qkv_kernel(
    const float* __restrict__ x,
    const float* __restrict__ Wq, const float* __restrict__ bq,
    const float* __restrict__ Wk, const float* __restrict__ bk,
    const float* __restrict__ Wv, const float* __restrict__ bv,
    float* __restrict__ vout, int n)
{
    // 144B row stride: ldmatrix 8-row groups hit distinct 16B chunks (9r mod 8).
    __shared__ __align__(16) __half sx[64][72];
    __shared__ __align__(16) __half sW[64][72];
    __shared__ float sbias[64];
    __shared__ float sstage[4][16][68];   // v epilogue staging (per warp)

    const int tid  = threadIdx.x;
    const int wid  = tid >> 5;
    const int lane = tid & 31;
    const int m    = blockIdx.y;
    const int base = blockIdx.x * 64;

    // zero g_denom (edge kernel launches later)
    if (m == 0) {
        for (int i = blockIdx.x * 128 + tid; i < n * 4; i += gridDim.x * 128)
            g_denom[i] = 0.0f;
    }

    const float* __restrict__ W  = (m == 0) ? Wq : (m == 1) ? Wk : Wv;
    const float* __restrict__ bp = (m == 0) ? bq : (m == 1) ? bk : bv;

    // x tile -> fp16 smem (zero-pad past n)
    for (int i = tid; i < 64 * 16; i += 128) {
        const int row = i >> 4, c4 = i & 15;
        const int node = base + row;
        float4 v = (node < n) ? ((const float4*)x)[(size_t)node * 16 + c4]
                              : make_float4(0.f, 0.f, 0.f, 0.f);
        const __half2 h0 = __floats2half2_rn(v.x, v.y);
        const __half2 h1 = __floats2half2_rn(v.z, v.w);
        uint2 pk;
        pk.x = *(const uint32_t*)&h0;
        pk.y = *(const uint32_t*)&h1;
        *(uint2*)&sx[row][c4 * 4] = pk;
    }
    // W tile -> fp16 smem (row-major [k][j], as in input)
    for (int i = tid; i < 64 * 16; i += 128) {
        const int k = i >> 4, c4 = i & 15;
        float4 v = ((const float4*)W)[k * 16 + c4];
        const __half2 h0 = __floats2half2_rn(v.x, v.y);
        const __half2 h1 = __floats2half2_rn(v.z, v.w);
        uint2 pk;
        pk.x = *(const uint32_t*)&h0;
        pk.y = *(const uint32_t*)&h1;
        *(uint2*)&sW[k][c4 * 4] = pk;
    }
    if (tid < 64) sbias[tid] = bp[tid];
    __syncthreads();

    // A fragments: 4 k-chunks of x[m0..m0+16) x k16
    const int m0 = wid * 16;
    uint32_t A[4][4];
    {
        const int arow = m0 + (lane & 15);
        const int acol = (lane >> 4) * 8;
#pragma unroll
        for (int kc = 0; kc < 4; kc++) {
            const uint32_t addr = smem_u32(&sx[arow][kc * 16 + acol]);
            asm volatile("ldmatrix.sync.aligned.m8n8.x4.shared.b16 "
                         "{%0,%1,%2,%3}, [%4];"
                         : "=r"(A[kc][0]), "=r"(A[kc][1]),
                           "=r"(A[kc][2]), "=r"(A[kc][3])
                         : "r"(addr));
        }
    }

    const int r0 = lane >> 2;
    const int cj = (lane & 3) * 2;
    const int n0 = base + m0 + r0;
    const int n1 = n0 + 8;

#pragma unroll
    for (int nt = 0; nt < 8; nt++) {
        float c0 = 0.f, c1 = 0.f, c2 = 0.f, c3 = 0.f;
#pragma unroll
        for (int kc = 0; kc < 4; kc++) {
            uint32_t b0, b1;
            const uint32_t addr = smem_u32(&sW[kc * 16 + (lane & 15)][nt * 8]);
            asm volatile("ldmatrix.sync.aligned.m8n8.x2.trans.shared.b16 "
                         "{%0,%1}, [%2];"
                         : "=r"(b0), "=r"(b1) : "r"(addr));
            asm volatile("mma.sync.aligned.m16n8k16.row.col.f32.f16.f16.f32 "
                         "{%0,%1,%2,%3}, {%4,%5,%6,%7}, {%8,%9}, {%0,%1,%2,%3};"
                         : "+f"(c0), "+f"(c1), "+f"(c2), "+f"(c3)
                         : "r"(A[kc][0]), "r"(A[kc][1]),
                           "r"(A[kc][2]), "r"(A[kc][3]),
                           "r"(b0), "r"(b1));
        }
        const int j = nt * 8 + cj;
        const float bj0 = sbias[j], bj1 = sbias[j + 1];
        if (m == 2) {
            sstage[wid][r0][j]         = c0 + bj0;
            sstage[wid][r0][j + 1]     = c1 + bj1;
            sstage[wid][r0 + 8][j]     = c2 + bj0;
            sstage[wid][r0 + 8][j + 1] = c3 + bj1;
        } else {
            __half* __restrict__ dst = (m == 0) ? g_qh : g_kh;
            if (n0 < n) {
                const __half2 h = __floats2half2_rn(c0 + bj0, c1 + bj1);
                *(__half2*)&dst[(size_t)n0 * 64 + j] = h;
            }
            if (n1 < n) {
                const __half2 h = __floats2half2_rn(c2 + bj0, c3 + bj1);
                *(__half2*)&dst[(size_t)n1 * 64 + j] = h;
            }
        }
    }

    if (m == 2) {
        __syncwarp();
        // v heads layout [N, d_k, nhead]: out float4 at dk = {j=h*16+dk, h=0..3}
        for (int i = lane; i < 16 * 16; i += 32) {
            const int r = i >> 4, dk = i & 15;
            const int node = base + m0 + r;
            if (node < n) {
                float4 o;
                o.x = sstage[wid][r][dk];
                o.y = sstage[wid][r][16 + dk];
                o.z = sstage[wid][r][32 + dk];
                o.w = sstage[wid][r][48 + dk];
                ((float4*)vout)[(size_t)node * 16 + dk] = o;
            }
        }
    }
}

// Edge pass, octet-cooperative (8 threads/edge). fp16 rows: 128B each.
// Thread d loads halfs [8d, 8d+8) via ONE LDG.128 per row (2 loads total);
// each warp instruction = 4 edges x one full 128B line -> 2 wavefronts/edge.
// Head h lives on lane pair {2h, 2h+1}: one shfl_xor(1) completes the dot.
__global__ void __launch_bounds__(256) edge_kernel(
    const int* __restrict__ e_src, const int* __restrict__ e_dst,
    float4* __restrict__ prods, int E)
{
    const int t = blockIdx.x * 256 + threadIdx.x;
    const int e = t >> 3;
    const int d = t & 7;
    const bool live = (e < E);
    const int ec = live ? e : (E - 1);

    const int s  = e_src[ec];
    const int td = e_dst[ec];

    const uint4* qp = reinterpret_cast<const uint4*>(g_qh + (size_t)s * 64);
    const uint4* kp = reinterpret_cast<const uint4*>(g_kh + (size_t)td * 64);

    const uint4 qv = qp[d];  // halfs [8d, 8d+8)
    const uint4 kv = kp[d];

    const float2 q0 = __half22float2(*(const __half2*)&qv.x);
    const float2 q1 = __half22float2(*(const __half2*)&qv.y);
    const float2 q2 = __half22float2(*(const __half2*)&qv.z);
    const float2 q3 = __half22float2(*(const __half2*)&qv.w);
    const float2 k0 = __half22float2(*(const __half2*)&kv.x);
    const float2 k1 = __half22float2(*(const __half2*)&kv.y);
    const float2 k2 = __half22float2(*(const __half2*)&kv.z);
    const float2 k3 = __half22float2(*(const __half2*)&kv.w);

    float acc = q0.x * k0.x + q0.y * k0.y + q1.x * k1.x + q1.y * k1.y
              + q2.x * k2.x + q2.y * k2.y + q3.x * k3.x + q3.y * k3.y;

    acc += __shfl_xor_sync(0xFFFFFFFFu, acc, 1);  // lanes 2h,2h+1 -> head-h dot

    const float p = acc * 0.25f;  // / sqrt(d_k=16)
    const float ex = __expf(p);

    // gather heads 1..3 (lanes obase+2h) into lane d==0 for the float4 store
    const int lane = threadIdx.x & 31;
    const int obase = lane & ~7;
    const float p1 = __shfl_sync(0xFFFFFFFFu, p, obase + 2);
    const float p2 = __shfl_sync(0xFFFFFFFFu, p, obase + 4);
    const float p3 = __shfl_sync(0xFFFFFFFFu, p, obase + 6);

    if (live) {
        if (d == 0) prods[e] = make_float4(p, p1, p2, p3);
        if ((d & 1) == 0)  // lanes 0,2,4,6 of octet: one REDG, 4 active/octet
            atomicAdd(&g_denom[s * 4 + (d >> 1)], ex);
    }
}

// Normalize: att[e] = exp(prods[e]) / denom. 2 edges per thread.
__global__ void __launch_bounds__(256) norm_kernel(
    const int* __restrict__ e_src, const float4* __restrict__ prods,
    float4* __restrict__ att, int E)
{
    const int base = (blockIdx.x * 256 + threadIdx.x) * 2;
#pragma unroll
    for (int u = 0; u < 2; u++) {
        const int e = base + u;
        if (e >= E) return;
        const int s = e_src[e];
        const float4 p = prods[e];
        const float4 dn = *reinterpret_cast<const float4*>(g_denom + s * 4);
        float4 a;
        a.x = __fdividef(__expf(p.x), dn.x + 1e-16f);
        a.y = __fdividef(__expf(p.y), dn.y + 1e-16f);
        a.z = __fdividef(__expf(p.z), dn.z + 1e-16f);
        a.w = __fdividef(__expf(p.w), dn.w + 1e-16f);
        att[e] = a;
    }
}

extern "C" void kernel_launch(void* const* d_in, const int* in_sizes, int n_in,
                              void* d_out, int out_size)
{
    const float* x  = (const float*)d_in[0];
    const int* edge = (const int*)d_in[1];
    const float* Wq = (const float*)d_in[2];
    const float* bq = (const float*)d_in[3];
    const float* Wk = (const float*)d_in[4];
    const float* bk = (const float*)d_in[5];
    const float* Wv = (const float*)d_in[6];
    const float* bv = (const float*)d_in[7];

    const int n = in_sizes[0] / NATT;   // 50000
    const int E = in_sizes[1] / 2;      // 1600000

    float* out   = (float*)d_out;
    float* att   = out;                                   // [E,4]
    float* vout  = out + (size_t)E * 4;                   // [N,16,4]
    float* prods = out + (size_t)E * 4 + (size_t)n * 64;  // [E,4]

    const int qblocks = (n + 63) / 64;  // 782
    dim3 qgrid(qblocks, 3);
    qkv_kernel<<<qgrid, 128>>>(x, Wq, bq, Wk, bk, Wv, bv, vout, n);

    const int eblocks = (int)(((long long)E * 8 + 255) / 256);
    edge_kernel<<<eblocks, 256>>>(edge, edge + E, (float4*)prods, E);

    const int nblocks = (E + 511) / 512;
    norm_kernel<<<nblocks, 256>>>(edge, (const float4*)prods, (float4*)att, E);
}

// round 17
// speedup vs baseline: 1.4550x; 1.4550x over previous
#include <cuda_runtime.h>
#include <cuda_fp16.h>
#include <cstdint>

// SpGraphTransAttention on GB300.
// Outputs (flattened tuple): attention [E,4] | v [N,16,4] | prods [E,4]
// Softmax identity: exp(p-max)/sum == exp(p)/sum (p tiny) -> no max pass.
// QKV on tensor cores (ldmatrix + mma.sync.m16n8k16, f16 in / f32 acc),
// ONE block does q,k,v for 64 nodes: x loaded once, A-frags reused 3x.
// q,k stored fp16 (128B rows); edge gathers one 128B line per row per edge.

#define NN_MAX 50000
#define NATT 64

__device__ __half g_qh[NN_MAX * NATT];
__device__ __half g_kh[NN_MAX * NATT];
__device__ float  g_denom[NN_MAX * 4];

__device__ __forceinline__ uint32_t smem_u32(const void* p) {
    return (uint32_t)__cvta_generic_to_shared(p);
}

// Grid: ceil(n/64) blocks x 128 threads. Warp w owns node rows [16w, 16w+16).
__global__ void __launch_bounds__(128) qkv_kernel(
    const float* __restrict__ x,
    const float* __restrict__ Wq, const float* __restrict__ bq,
    const float* __restrict__ Wk, const float* __restrict__ bk,
    const float* __restrict__ Wv, const float* __restrict__ bv,
    float* __restrict__ vout, int n)
{
    // 144B row stride: ldmatrix 8-row groups hit distinct 16B chunks.
    __shared__ __align__(16) __half sx[64][72];        // 9216 B
    __shared__ __align__(16) __half sW[3][64][72];     // 27648 B
    __shared__ float sbias[3][64];                     // 768 B
    __shared__ __align__(16) float sstage[4][8][68];   // 8704 B (v epilogue)

    const int tid  = threadIdx.x;
    const int wid  = tid >> 5;
    const int lane = tid & 31;
    const int base = blockIdx.x * 64;

    // zero g_denom (edge kernel launches later); grid-stride
    for (int i = blockIdx.x * 128 + tid; i < n * 4; i += gridDim.x * 128)
        g_denom[i] = 0.0f;

    // x tile -> fp16 smem (zero-pad past n) -- loaded ONCE for q,k,v
    for (int i = tid; i < 64 * 16; i += 128) {
        const int row = i >> 4, c4 = i & 15;
        const int node = base + row;
        float4 v = (node < n) ? ((const float4*)x)[(size_t)node * 16 + c4]
                              : make_float4(0.f, 0.f, 0.f, 0.f);
        const __half2 h0 = __floats2half2_rn(v.x, v.y);
        const __half2 h1 = __floats2half2_rn(v.z, v.w);
        uint2 pk;
        pk.x = *(const uint32_t*)&h0;
        pk.y = *(const uint32_t*)&h1;
        *(uint2*)&sx[row][c4 * 4] = pk;
    }
    // all three W tiles -> fp16 smem
    {
        const float* __restrict__ Ws[3] = {Wq, Wk, Wv};
#pragma unroll
        for (int mm = 0; mm < 3; mm++) {
            const float* __restrict__ W = Ws[mm];
            for (int i = tid; i < 64 * 16; i += 128) {
                const int k = i >> 4, c4 = i & 15;
                float4 v = ((const float4*)W)[k * 16 + c4];
                const __half2 h0 = __floats2half2_rn(v.x, v.y);
                const __half2 h1 = __floats2half2_rn(v.z, v.w);
                uint2 pk;
                pk.x = *(const uint32_t*)&h0;
                pk.y = *(const uint32_t*)&h1;
                *(uint2*)&sW[mm][k][c4 * 4] = pk;
            }
        }
    }
    if (tid < 64) {
        sbias[0][tid] = bq[tid];
        sbias[1][tid] = bk[tid];
        sbias[2][tid] = bv[tid];
    }
    __syncthreads();

    // A fragments (built once, reused for all 3 GEMMs)
    const int m0 = wid * 16;
    uint32_t A[4][4];
    {
        const int arow = m0 + (lane & 15);
        const int acol = (lane >> 4) * 8;
#pragma unroll
        for (int kc = 0; kc < 4; kc++) {
            const uint32_t addr = smem_u32(&sx[arow][kc * 16 + acol]);
            asm volatile("ldmatrix.sync.aligned.m8n8.x4.shared.b16 "
                         "{%0,%1,%2,%3}, [%4];"
                         : "=r"(A[kc][0]), "=r"(A[kc][1]),
                           "=r"(A[kc][2]), "=r"(A[kc][3])
                         : "r"(addr));
        }
    }

    const int r0 = lane >> 2;
    const int cj = (lane & 3) * 2;
    const int n0 = base + m0 + r0;
    const int n1 = n0 + 8;

    float vacc[8][4];  // v accumulators held in registers across nt

#pragma unroll
    for (int m = 0; m < 3; m++) {
#pragma unroll
        for (int nt = 0; nt < 8; nt++) {
            float c0 = 0.f, c1 = 0.f, c2 = 0.f, c3 = 0.f;
#pragma unroll
            for (int kc = 0; kc < 4; kc++) {
                uint32_t b0, b1;
                const uint32_t addr =
                    smem_u32(&sW[m][kc * 16 + (lane & 15)][nt * 8]);
                asm volatile("ldmatrix.sync.aligned.m8n8.x2.trans.shared.b16 "
                             "{%0,%1}, [%2];"
                             : "=r"(b0), "=r"(b1) : "r"(addr));
                asm volatile(
                    "mma.sync.aligned.m16n8k16.row.col.f32.f16.f16.f32 "
                    "{%0,%1,%2,%3}, {%4,%5,%6,%7}, {%8,%9}, {%0,%1,%2,%3};"
                    : "+f"(c0), "+f"(c1), "+f"(c2), "+f"(c3)
                    : "r"(A[kc][0]), "r"(A[kc][1]),
                      "r"(A[kc][2]), "r"(A[kc][3]),
                      "r"(b0), "r"(b1));
            }
            const int j = nt * 8 + cj;
            const float bj0 = sbias[m][j], bj1 = sbias[m][j + 1];
            if (m == 2) {
                vacc[nt][0] = c0 + bj0;
                vacc[nt][1] = c1 + bj1;
                vacc[nt][2] = c2 + bj0;
                vacc[nt][3] = c3 + bj1;
            } else {
                __half* __restrict__ dst = (m == 0) ? g_qh : g_kh;
                if (n0 < n) {
                    const __half2 h = __floats2half2_rn(c0 + bj0, c1 + bj1);
                    *(__half2*)&dst[(size_t)n0 * 64 + j] = h;
                }
                if (n1 < n) {
                    const __half2 h = __floats2half2_rn(c2 + bj0, c3 + bj1);
                    *(__half2*)&dst[(size_t)n1 * 64 + j] = h;
                }
            }
        }
    }

    // v epilogue: two 8-row staging passes per warp, coalesced float4 stores.
    // Heads layout [N, d_k, nhead]: col j=h*16+dk -> stage index dk*4+h.
#pragma unroll
    for (int half = 0; half < 2; half++) {
        __syncwarp();
#pragma unroll
        for (int nt = 0; nt < 8; nt++) {
            const int j = nt * 8 + cj;
            const float a = vacc[nt][half * 2];
            const float b = vacc[nt][half * 2 + 1];
            sstage[wid][r0][(j & 15) * 4 + (j >> 4)]           = a;
            sstage[wid][r0][((j + 1) & 15) * 4 + ((j + 1) >> 4)] = b;
        }
        __syncwarp();
        for (int i = lane; i < 8 * 16; i += 32) {
            const int r = i >> 4, c4 = i & 15;
            const int node = base + m0 + half * 8 + r;
            if (node < n)
                ((float4*)vout)[(size_t)node * 16 + c4] =
                    *(const float4*)&sstage[wid][r][c4 * 4];
        }
    }
}

// Edge pass, octet-cooperative (8 threads/edge). fp16 rows: 128B each.
// Thread d loads halfs [8d, 8d+8) via ONE LDG.128 per row (2 loads total);
// each warp instruction = 4 edges x one full 128B line -> 2 wavefronts/edge.
// Head h lives on lane pair {2h, 2h+1}: one shfl_xor(1) completes the dot.
__global__ void __launch_bounds__(256) edge_kernel(
    const int* __restrict__ e_src, const int* __restrict__ e_dst,
    float4* __restrict__ prods, int E)
{
    const int t = blockIdx.x * 256 + threadIdx.x;
    const int e = t >> 3;
    const int d = t & 7;
    const bool live = (e < E);
    const int ec = live ? e : (E - 1);

    const int s  = e_src[ec];
    const int td = e_dst[ec];

    const uint4* qp = reinterpret_cast<const uint4*>(g_qh + (size_t)s * 64);
    const uint4* kp = reinterpret_cast<const uint4*>(g_kh + (size_t)td * 64);

    const uint4 qv = qp[d];  // halfs [8d, 8d+8)
    const uint4 kv = kp[d];

    const float2 q0 = __half22float2(*(const __half2*)&qv.x);
    const float2 q1 = __half22float2(*(const __half2*)&qv.y);
    const float2 q2 = __half22float2(*(const __half2*)&qv.z);
    const float2 q3 = __half22float2(*(const __half2*)&qv.w);
    const float2 k0 = __half22float2(*(const __half2*)&kv.x);
    const float2 k1 = __half22float2(*(const __half2*)&kv.y);
    const float2 k2 = __half22float2(*(const __half2*)&kv.z);
    const float2 k3 = __half22float2(*(const __half2*)&kv.w);

    float acc = q0.x * k0.x + q0.y * k0.y + q1.x * k1.x + q1.y * k1.y
              + q2.x * k2.x + q2.y * k2.y + q3.x * k3.x + q3.y * k3.y;

    acc += __shfl_xor_sync(0xFFFFFFFFu, acc, 1);  // lanes 2h,2h+1 -> head-h dot

    const float p = acc * 0.25f;  // / sqrt(d_k=16)
    const float ex = __expf(p);

    // gather heads 1..3 (lanes obase+2h) into lane d==0 for the float4 store
    const int lane = threadIdx.x & 31;
    const int obase = lane & ~7;
    const float p1 = __shfl_sync(0xFFFFFFFFu, p, obase + 2);
    const float p2 = __shfl_sync(0xFFFFFFFFu, p, obase + 4);
    const float p3 = __shfl_sync(0xFFFFFFFFu, p, obase + 6);

    if (live) {
        if (d == 0) prods[e] = make_float4(p, p1, p2, p3);
        if ((d & 1) == 0)  // lanes 0,2,4,6 of octet: one REDG, 4 active/octet
            atomicAdd(&g_denom[s * 4 + (d >> 1)], ex);
    }
}

// Normalize: att[e] = exp(prods[e]) / denom. 2 edges per thread.
__global__ void __launch_bounds__(256) norm_kernel(
    const int* __restrict__ e_src, const float4* __restrict__ prods,
    float4* __restrict__ att, int E)
{
    const int base = (blockIdx.x * 256 + threadIdx.x) * 2;
#pragma unroll
    for (int u = 0; u < 2; u++) {
        const int e = base + u;
        if (e >= E) return;
        const int s = e_src[e];
        const float4 p = prods[e];
        const float4 dn = *reinterpret_cast<const float4*>(g_denom + s * 4);
        float4 a;
        a.x = __fdividef(__expf(p.x), dn.x + 1e-16f);
        a.y = __fdividef(__expf(p.y), dn.y + 1e-16f);
        a.z = __fdividef(__expf(p.z), dn.z + 1e-16f);
        a.w = __fdividef(__expf(p.w), dn.w + 1e-16f);
        att[e] = a;
    }
}

extern "C" void kernel_launch(void* const* d_in, const int* in_sizes, int n_in,
                              void* d_out, int out_size)
{
    const float* x  = (const float*)d_in[0];
    const int* edge = (const int*)d_in[1];
    const float* Wq = (const float*)d_in[2];
    const float* bq = (const float*)d_in[3];
    const float* Wk = (const float*)d_in[4];
    const float* bk = (const float*)d_in[5];
    const float* Wv = (const float*)d_in[6];
    const float* bv = (const float*)d_in[7];

    const int n = in_sizes[0] / NATT;   // 50000
    const int E = in_sizes[1] / 2;      // 1600000

    float* out   = (float*)d_out;
    float* att   = out;                                   // [E,4]
    float* vout  = out + (size_t)E * 4;                   // [N,16,4]
    float* prods = out + (size_t)E * 4 + (size_t)n * 64;  // [E,4]

    const int qblocks = (n + 63) / 64;  // 782
    qkv_kernel<<<qblocks, 128>>>(x, Wq, bq, Wk, bk, Wv, bv, vout, n);

    const int eblocks = (int)(((long long)E * 8 + 255) / 256);
    edge_kernel<<<eblocks, 256>>>(edge, edge + E, (float4*)prods, E);

    const int nblocks = (E + 511) / 512;
    norm_kernel<<<nblocks, 256>>>(edge, (const float4*)prods, (float4*)att, E);
}